// round 16
// baseline (speedup 1.0000x reference)
#include <cuda_runtime.h>
#include <cuda_bf16.h>
#include <cstdint>

// Closed-form per-(batch,class) reduction of the symmetric-pair loss.
// For a group of n points of one symmetric class (c in {0,1,2}), with
// u_i = x_i - CENTER_X:
//   sum_{i<j} (u_i+u_j)^2 = (n-2)*Sum(u^2) + (Sum u)^2
//   sum_{i<j} (y_i-y_j)^2 =  n   *Sum(y^2) - (Sum y)^2
//   #pairs                =  n(n-1)/2
// Both identities are exactly 0 for n in {0,1}.
//
// SINGLE kernel, SINGLE packed atomic per batch (R13 finalize):
//   packed = (1 << 55) | (round(loss * 8) << 25) | count
//   count  <= 256*C(512,2) = 33,488,896 < 2^25   -> bits [24:0]
//   loss*8 < 2^30                                 -> bits [54:25]
//   ticket sum = 256 < 2^9                        -> bits [63:55]
// Integer addition is order-invariant -> deterministic. The finalizer
// whose returned 'old' shows ticket==255 already holds the grand total.
//
// R15 shape probe: 128 CTAs x 256 threads; each CTA = 2 independent
// 128-thread batch groups (4 points/thread, R14-proven data path).
// Sub-single-wave grid: every SM gets at most one CTA.

#define CENTER_X 0.5f
#define BATCH 256
#define NPTS  512
#define TPB   256
#define LOSS_SCALE 8.0           // 2^3
#define CNT_BITS   25
#define CNT_MASK   ((1ull << CNT_BITS) - 1ull)
#define LOSS_MASK  ((1ull << 30) - 1ull)
#define TICKET_SHIFT 55

__device__ unsigned long long g_pack = 0;  // ticket | loss_fx | count

__global__ void __launch_bounds__(TPB) sym_fused(const float* __restrict__ kp,
                                                 const int* __restrict__ cls,
                                                 float* __restrict__ out) {
    const int t   = threadIdx.x;
    const int grp = t >> 7;          // batch group within CTA: 0 or 1
    const int tg  = t & 127;         // thread within group
    const int b   = blockIdx.x * 2 + grp;

    // Each thread handles 4 consecutive points: 2x float4 + 1x int4.
    const float4* kp4 = reinterpret_cast<const float4*>(kp) + (size_t)b * 256;
    const float4 pA = kp4[2 * tg];
    const float4 pB = kp4[2 * tg + 1];
    const int4   c4 = reinterpret_cast<const int4*>(cls)[(size_t)b * 128 + tg];

    float acc[12];  // [class][su, su2, sy, sy2]
#pragma unroll
    for (int k = 0; k < 12; k++) acc[k] = 0.0f;

    const float ux[4] = {pA.x - CENTER_X, pA.z - CENTER_X,
                         pB.x - CENTER_X, pB.z - CENTER_X};
    const float yy[4] = {pA.y, pA.w, pB.y, pB.w};
    const int   cc[4] = {c4.x, c4.y, c4.z, c4.w};

    int wcnt[3];  // warp-level class counts via ballot (uniform across lanes)
#pragma unroll
    for (int k = 0; k < 3; k++) {
        int n = 0;
#pragma unroll
        for (int j = 0; j < 4; j++)
            n += __popc(__ballot_sync(0xffffffffu, cc[j] == k));
        wcnt[k] = n;
    }

#pragma unroll
    for (int j = 0; j < 4; j++) {
#pragma unroll
        for (int k = 0; k < 3; k++) {
            if (cc[j] == k) {
                acc[k * 4 + 0] += ux[j];
                acc[k * 4 + 1]  = fmaf(ux[j], ux[j], acc[k * 4 + 1]);
                acc[k * 4 + 2] += yy[j];
                acc[k * 4 + 3]  = fmaf(yy[j], yy[j], acc[k * 4 + 3]);
            }
        }
    }

    // Intra-warp reduction (shuffles): 12 float accumulators.
#pragma unroll
    for (int off = 16; off > 0; off >>= 1) {
#pragma unroll
        for (int k = 0; k < 12; k++)
            acc[k] += __shfl_down_sync(0xffffffffu, acc[k], off);
    }

    // Cross-warp via shared memory: warps 0-3 = group 0, warps 4-7 = group 1.
    __shared__ float sf[8][16];    // padded rows
    __shared__ float stot[2][16];
    const int wid = t >> 5, lid = t & 31;
    if (lid == 0) {
#pragma unroll
        for (int k = 0; k < 12; k++) sf[wid][k] = acc[k];
#pragma unroll
        for (int k = 0; k < 3; k++)  sf[wid][12 + k] = (float)wcnt[k];
    }
    __syncthreads();

    // Warp 0 finalizes group 0; warp 4 finalizes group 1. Parallel, no
    // extra synchronization: each does its own packed atomic.
    if ((wid & 3) == 0) {
        const int g    = wid >> 2;      // 0 or 1
        const int base = g * 4;         // first warp row of this group
        if (lid < 15) {
            float s = 0.0f;
#pragma unroll
            for (int w = 0; w < 4; w++) s += sf[base + w][lid];
            stot[g][lid] = s;
        }
        __syncwarp();
        if (lid == 0) {
            float loss = 0.0f, count = 0.0f;
#pragma unroll
            for (int k = 0; k < 3; k++) {
                const float SU  = stot[g][k * 4 + 0];
                const float SU2 = stot[g][k * 4 + 1];
                const float SY  = stot[g][k * 4 + 2];
                const float SY2 = stot[g][k * 4 + 3];
                const float n   = stot[g][12 + k];
                loss  += (n - 2.0f) * SU2 + SU * SU + n * SY2 - SY * SY;
                count += n * (n - 1.0f) * 0.5f;
            }
            // ONE packed deterministic atomic per batch; return value is
            // both completion detection and the grand total.
            const unsigned long long lfx =
                (unsigned long long)llrint((double)loss * LOSS_SCALE);
            const unsigned long long cu =
                (unsigned long long)llrintf(count);  // exact integer
            const unsigned long long mine =
                (1ull << TICKET_SHIFT) | (lfx << CNT_BITS) | cu;
            const unsigned long long old = atomicAdd(&g_pack, mine);

            if ((old >> TICKET_SHIFT) == (unsigned long long)(BATCH - 1)) {
                const unsigned long long total = old + mine;
                const double loss_d =
                    (double)((total >> CNT_BITS) & LOSS_MASK) / LOSS_SCALE;
                const unsigned long long C = total & CNT_MASK;
                const double cnt_d = (C < 1ull) ? 1.0 : (double)C;
                out[0] = (float)(loss_d / cnt_d);
                g_pack = 0ull;  // reset for next graph replay (deterministic)
            }
        }
    }
}

extern "C" void kernel_launch(void* const* d_in, const int* in_sizes, int n_in,
                              void* d_out, int out_size) {
    const float* kp  = (const float*)d_in[0];  // [256, 512, 2] f32
    const int*   cls = (const int*)d_in[1];    // [256, 512] i32
    float* out = (float*)d_out;

    sym_fused<<<BATCH / 2, TPB>>>(kp, cls, out);
}